// round 1
// baseline (speedup 1.0000x reference)
#include <cuda_runtime.h>
#include <cstdint>
#include <math.h>

#define BB 32
#define SS 128
#define DD 512
#define NN 131072
#define RR 16
#define KK 8

#define NBLK 128
#define KC 64
#define BST 66   // base tile row stride in floats (conflict-free LDS.64)

typedef unsigned long long ull;

// ---------------- scratch (device globals; no allocation allowed) -------------
__device__ float g_q[BB * DD];
__device__ float g_qB[BB * RR];
__device__ float g_scores[(size_t)BB * NN];
__device__ int   g_topidx[BB * KK];
__device__ float g_xsum[BB * DD];
__device__ float g_gx[3 * DD * BB];   // g_gx[j*32 + b]
__device__ float g_wp[BB];

__device__ __forceinline__ ull fma2(ull a, ull b, ull c) {
    ull d;
    asm("fma.rn.f32x2 %0, %1, %2, %3;" : "=l"(d) : "l"(a), "l"(b), "l"(c));
    return d;
}
__device__ __forceinline__ float lo32(ull x) { return __int_as_float((int)(x & 0xffffffffu)); }
__device__ __forceinline__ float hi32(ull x) { return __int_as_float((int)(x >> 32)); }

__device__ __forceinline__ float sigmoidf_(float x) { return 1.f / (1.f + expf(-x)); }

// ---------------- kernel 1: q = mean_s(query); qB = q @ lora_B.T --------------
__global__ void k_qmean(const float* __restrict__ query, const float* __restrict__ loraB) {
    int b = blockIdx.x, t = threadIdx.x;          // 512 threads
    __shared__ float qs[DD];
    float s = 0.f;
    const float* qp = query + (size_t)b * SS * DD + t;
#pragma unroll 8
    for (int i = 0; i < SS; i++) s += qp[(size_t)i * DD];
    s *= (1.f / 128.f);
    qs[t] = s;
    g_q[b * DD + t] = s;
    __syncthreads();
    int w = t >> 5, lane = t & 31;                // 16 warps == RR
    float acc = 0.f;
    for (int i = lane; i < DD; i += 32) acc += qs[i] * loraB[w * DD + i];
#pragma unroll
    for (int o = 16; o; o >>= 1) acc += __shfl_xor_sync(0xffffffffu, acc, o);
    if (lane == 0) g_qB[b * RR + w] = acc;
}

// ---------------- kernel 2: fused scores GEMM + new_mem copy ------------------
// scores[b][n] = dot(q[b], base[n]) + sum_r qB[b][r]*A[n][r];   newmem[n] = base[n]
__global__ void __launch_bounds__(256, 2) k_main(const float* __restrict__ base,
                                                 const float* __restrict__ loraA,
                                                 float* __restrict__ newmem) {
    extern __shared__ float sm[];
    float* q_s  = sm;                       // 32*512       = 16384 f
    float* bs   = sm + BB * DD;             // 128*66       =  8448 f
    float* A_s  = bs + NBLK * BST;          // 128*16       =  2048 f
    float* qB_s = A_s + NBLK * RR;          // 32*16        =   512 f

    int tid = threadIdx.x;
    int n0  = blockIdx.x * NBLK;

    // stage q (fp32, full)  — q is 64 KB total, L2-resident across the grid
    {
        const float4* src = (const float4*)g_q;
        float4* dst = (float4*)q_s;
        for (int i = tid; i < BB * DD / 4; i += 256) dst[i] = src[i];
    }
    // stage A tile + qB
    for (int i = tid; i < NBLK * RR; i += 256) A_s[i] = loraA[(size_t)n0 * RR + i];
    for (int i = tid; i < BB * RR; i += 256) qB_s[i] = g_qB[i];

    int rg = tid & 31, bg = tid >> 5;       // warp = batch-group, lane = row-group
    ull acc[4][4];
#pragma unroll
    for (int bt = 0; bt < 4; bt++)
#pragma unroll
        for (int rt = 0; rt < 4; rt++) acc[bt][rt] = 0ull;

    for (int c = 0; c < DD / KC; c++) {
        int kc0 = c * KC;
        __syncthreads();
        // load base tile into smem + copy straight through to new_mem
        for (int i = tid; i < NBLK * KC / 4; i += 256) {
            int row = i >> 4, c4 = i & 15;
            size_t g = (size_t)(n0 + row) * DD + kc0 + c4 * 4;
            const float4 v = *(const float4*)&base[g];
            *(float4*)&newmem[g] = v;
            ull* p = (ull*)&bs[row * BST + c4 * 4];   // 8B-aligned (264B row stride)
            p[0] = ((const ull*)&v)[0];
            p[1] = ((const ull*)&v)[1];
        }
        __syncthreads();
#pragma unroll
        for (int kp = 0; kp < KC / 2; kp++) {
            ull qv[4], bv[4];
#pragma unroll
            for (int bt = 0; bt < 4; bt++)
                qv[bt] = *(const ull*)&q_s[(bg * 4 + bt) * DD + kc0 + kp * 2];
#pragma unroll
            for (int rt = 0; rt < 4; rt++)
                bv[rt] = *(const ull*)&bs[(rg + 32 * rt) * BST + kp * 2];
#pragma unroll
            for (int bt = 0; bt < 4; bt++)
#pragma unroll
                for (int rt = 0; rt < 4; rt++)
                    acc[bt][rt] = fma2(qv[bt], bv[rt], acc[bt][rt]);
        }
    }

#pragma unroll
    for (int bt = 0; bt < 4; bt++) {
        int b = bg * 4 + bt;
#pragma unroll
        for (int rt = 0; rt < 4; rt++) {
            int rl = rg + 32 * rt;
            float s = lo32(acc[bt][rt]) + hi32(acc[bt][rt]);
            float l = 0.f;
#pragma unroll
            for (int r = 0; r < RR; r++) l += qB_s[b * RR + r] * A_s[rl * RR + r];
            g_scores[(size_t)b * NN + n0 + rl] = s + l;
        }
    }
}

// ---------------- kernel 3: top-8 per batch (JAX semantics) -------------------
__device__ __forceinline__ bool better(float v1, int i1, float v2, int i2) {
    return (v1 > v2) || (v1 == v2 && i1 < i2);
}
__global__ void k_topk() {
    int b = blockIdx.x, tid = threadIdx.x;   // 1024 threads
    extern __shared__ float sm[];
    float* sval = sm;                         // 8192
    int*   sidx = (int*)(sm + 8192);          // 8192
    float* rv   = sm + 16384;                 // 1024
    int*   ri   = (int*)(sm + 17408);         // 1024
    int*   rs   = (int*)(sm + 18432);         // 1024

    const float* sc = g_scores + (size_t)b * NN;
    const float NEG = -__int_as_float(0x7f800000);
    float v[8]; int ix[8];
#pragma unroll
    for (int i = 0; i < 8; i++) { v[i] = NEG; ix[i] = 0x7fffffff; }

    for (int i = 0; i < NN / 1024; i++) {
        int n = tid + (i << 10);
        float x = sc[n];
        if (x > v[7]) {
            v[7] = x; ix[7] = n;
#pragma unroll
            for (int j = 7; j >= 1; j--) {
                if (v[j] > v[j - 1]) {
                    float tv = v[j - 1]; int ti = ix[j - 1];
                    v[j - 1] = v[j]; ix[j - 1] = ix[j];
                    v[j] = tv; ix[j] = ti;
                }
            }
        }
    }
#pragma unroll
    for (int i = 0; i < 8; i++) { sval[tid * 8 + i] = v[i]; sidx[tid * 8 + i] = ix[i]; }
    __syncthreads();

    for (int r = 0; r < KK; r++) {
        float bv = NEG; int bi = 0x7fffffff; int bslot = tid * 8;
#pragma unroll
        for (int i = 0; i < 8; i++) {
            int s = tid * 8 + i;
            if (better(sval[s], sidx[s], bv, bi)) { bv = sval[s]; bi = sidx[s]; bslot = s; }
        }
        rv[tid] = bv; ri[tid] = bi; rs[tid] = bslot;
        __syncthreads();
        for (int s = 512; s > 0; s >>= 1) {
            if (tid < s) {
                if (better(rv[tid + s], ri[tid + s], rv[tid], ri[tid])) {
                    rv[tid] = rv[tid + s]; ri[tid] = ri[tid + s]; rs[tid] = rs[tid + s];
                }
            }
            __syncthreads();
        }
        if (tid == 0) {
            g_topidx[b * KK + r] = ri[0];
            sval[rs[0]] = NEG;   // remove winner
        }
        __syncthreads();
    }
}

// ---------------- kernel 4: retrieved rows (mem = base + A@B) + xsum ----------
__global__ void k_retr(const float* __restrict__ base, const float* __restrict__ loraA,
                       const float* __restrict__ loraB, float* __restrict__ out_retr) {
    int b = blockIdx.x, tid = threadIdx.x;   // 512 threads
    __shared__ float A_s[KK * RR];
    __shared__ float B_s[RR * DD];
    if (tid < KK * RR) {
        int k = tid >> 4, r = tid & 15;
        A_s[tid] = loraA[(size_t)g_topidx[b * KK + k] * RR + r];
    }
    for (int i = tid; i < RR * DD; i += 512) B_s[i] = loraB[i];
    __syncthreads();
    int d = tid;
    float x = 0.f;
    for (int k = 0; k < KK; k++) {
        int idx = g_topidx[b * KK + k];
        float vv = base[(size_t)idx * DD + d];
#pragma unroll
        for (int r = 0; r < RR; r++) vv += A_s[k * RR + r] * B_s[r * DD + d];
        out_retr[(size_t)(b * KK + k) * DD + d] = vv;
        x += vv;
    }
    g_xsum[b * DD + d] = x;
}

// ---------------- kernel 5: gx[j][b] = dot(xsum[b], w_ih[j]) ------------------
__global__ void k_gx(const float* __restrict__ w_ih) {
    extern __shared__ float xs[];            // 32*512 floats
    int tid = threadIdx.x;                   // 1024 threads
    for (int i = tid; i < BB * DD; i += 1024) xs[i] = g_xsum[i];
    __syncthreads();
    int w = tid >> 5, lane = tid & 31;
    int j = blockIdx.x * 32 + w;             // 48 blocks * 32 warps = 1536 rows
    const float* wr = w_ih + (size_t)j * DD;
    float acc[BB];
#pragma unroll
    for (int b = 0; b < BB; b++) acc[b] = 0.f;
    for (int kk = 0; kk < DD / 32; kk++) {
        float wv = wr[kk * 32 + lane];
#pragma unroll
        for (int b = 0; b < BB; b++) acc[b] += wv * xs[b * DD + kk * 32 + lane];
    }
#pragma unroll
    for (int b = 0; b < BB; b++) {
        float a = acc[b];
#pragma unroll
        for (int o = 16; o; o >>= 1) a += __shfl_xor_sync(0xffffffffu, a, o);
        if (lane == b) g_gx[j * 32 + b] = a;
    }
}

// ---------------- kernel 6: GRU gates -> hidden (h0 = 0) ----------------------
__global__ void k_hidden(const float* __restrict__ b_ih, const float* __restrict__ b_hh,
                         float* __restrict__ out_hidden) {
    int i = blockIdx.x * blockDim.x + threadIdx.x;
    if (i >= BB * DD) return;
    int b = i >> 9, d = i & 511;
    float gr = g_gx[(0 * DD + d) * 32 + b] + b_ih[d]        + b_hh[d];
    float gz = g_gx[(1 * DD + d) * 32 + b] + b_ih[DD + d]   + b_hh[DD + d];
    float gn = g_gx[(2 * DD + d) * 32 + b] + b_ih[2 * DD + d];
    float r = sigmoidf_(gr);
    float z = sigmoidf_(gz);
    float n = tanhf(gn + r * b_hh[2 * DD + d]);
    out_hidden[b * DD + d] = (1.f - z) * n;
}

// ---------------- kernel 7: write_prob ----------------------------------------
__global__ void k_wp(const float* __restrict__ hidden, const float* __restrict__ wg_w,
                     const float* __restrict__ wg_b) {
    int w = threadIdx.x >> 5, lane = threadIdx.x & 31;  // 32 warps = B
    float a = 0.f;
    for (int i = lane; i < DD; i += 32) a += hidden[w * DD + i] * wg_w[i];
#pragma unroll
    for (int o = 16; o; o >>= 1) a += __shfl_xor_sync(0xffffffffu, a, o);
    if (lane == 0) g_wp[w] = sigmoidf_(a + wg_b[0]);
}

// ---------------- kernel 8: sequential-over-batch scatter ---------------------
__global__ void k_scatter(float* __restrict__ newmem) {
    int tid = threadIdx.x;                    // 512 threads, single block
    for (int b = 0; b < BB; b++) {
        float p  = g_wp[b];
        float vq = g_q[b * DD + tid];
        for (int k = 0; k < KK; k++) {
            size_t row = (size_t)g_topidx[b * KK + k] * DD;
            newmem[row + tid] = (1.f - p) * newmem[row + tid] + p * vq;
        }
        __syncthreads();   // batch b+1 must see batch b's writes (cross-batch collisions)
    }
}

// ---------------- launch ------------------------------------------------------
extern "C" void kernel_launch(void* const* d_in, const int* in_sizes, int n_in,
                              void* d_out, int out_size) {
    const float* query = (const float*)d_in[0];
    const float* base  = (const float*)d_in[1];
    const float* loraA = (const float*)d_in[2];
    const float* loraB = (const float*)d_in[3];
    const float* w_ih  = (const float*)d_in[4];
    // d_in[5] = gru_w_hh : unused (h0 == 0)
    const float* b_ih  = (const float*)d_in[6];
    const float* b_hh  = (const float*)d_in[7];
    const float* wg_w  = (const float*)d_in[8];
    const float* wg_b  = (const float*)d_in[9];

    float* out        = (float*)d_out;
    float* out_retr   = out;                         // [32, 8, 512]
    float* out_hidden = out + BB * KK * DD;          // [32, 512]
    float* out_newmem = out + BB * KK * DD + BB * DD;// [131072, 512]

    const int MAIN_SMEM = (BB * DD + NBLK * BST + NBLK * RR + BB * RR) * 4; // 109,568 B
    const int TOPK_SMEM = (8192 * 2 + 1024 * 3) * 4;                        //  77,824 B
    const int GX_SMEM   = BB * DD * 4;                                      //  65,536 B
    cudaFuncSetAttribute(k_main, cudaFuncAttributeMaxDynamicSharedMemorySize, MAIN_SMEM);
    cudaFuncSetAttribute(k_topk, cudaFuncAttributeMaxDynamicSharedMemorySize, TOPK_SMEM);
    cudaFuncSetAttribute(k_gx,   cudaFuncAttributeMaxDynamicSharedMemorySize, GX_SMEM);

    k_qmean  <<<BB, DD>>>(query, loraB);
    k_main   <<<NN / NBLK, 256, MAIN_SMEM>>>(base, loraA, out_newmem);
    k_topk   <<<BB, 1024, TOPK_SMEM>>>();
    k_retr   <<<BB, DD>>>(base, loraA, loraB, out_retr);
    k_gx     <<<48, 1024, GX_SMEM>>>(w_ih);
    k_hidden <<<16, 1024>>>(b_ih, b_hh, out_hidden);
    k_wp     <<<1, 1024>>>(out_hidden, wg_w, wg_b);
    k_scatter<<<1, DD>>>(out_newmem);
}

// round 2
// speedup vs baseline: 1.2348x; 1.2348x over previous
#include <cuda_runtime.h>
#include <cstdint>
#include <math.h>

#define BB 32
#define SS 128
#define DD 512
#define NN 131072
#define RR 16
#define KK 8

#define NBLK 128
#define KC 64
#define BST 68   // base tile row stride in floats: 272B rows -> 16B-aligned, LDS.128 conflict-free

typedef unsigned long long ull;

// ---------------- scratch (device globals; no allocation allowed) -------------
__device__ float g_q[BB * DD];
__device__ float g_qpart[4 * BB * DD];
__device__ float g_qB[BB * RR];
__device__ float g_scores[(size_t)BB * NN];
__device__ int   g_topidx[BB * KK];
__device__ float g_gx[3 * DD * BB];   // g_gx[j*32 + b]
__device__ float g_wp[BB];

__device__ __forceinline__ ull fma2(ull a, ull b, ull c) {
    ull d;
    asm("fma.rn.f32x2 %0, %1, %2, %3;" : "=l"(d) : "l"(a), "l"(b), "l"(c));
    return d;
}
__device__ __forceinline__ float lo32(ull x) { return __int_as_float((int)(x & 0xffffffffu)); }
__device__ __forceinline__ float hi32(ull x) { return __int_as_float((int)(x >> 32)); }
__device__ __forceinline__ float sigmoidf_(float x) { return 1.f / (1.f + expf(-x)); }

__device__ __forceinline__ void cp16(void* dst_smem, const void* src) {
    unsigned s = (unsigned)__cvta_generic_to_shared(dst_smem);
    asm volatile("cp.async.cg.shared.global [%0], [%1], 16;" :: "r"(s), "l"(src) : "memory");
}

// ---------------- kernel 1a: partial sums of query over S ---------------------
__global__ void k_qsum(const float* __restrict__ query) {
    int b = blockIdx.x, g = blockIdx.y, t = threadIdx.x;   // 512 threads, grid (32,4)
    const float* qp = query + ((size_t)b * SS + g * 32) * DD + t;
    float s = 0.f;
#pragma unroll
    for (int i = 0; i < 32; i++) s += qp[(size_t)i * DD];
    g_qpart[(b * 4 + g) * DD + t] = s;
}

// ---------------- kernel 1b: finalize q, compute qB = q @ lora_B.T ------------
__global__ void k_qfin(const float* __restrict__ loraB) {
    int b = blockIdx.x, t = threadIdx.x;          // 512 threads
    __shared__ float qs[DD];
    float s = (g_qpart[(b * 4 + 0) * DD + t] + g_qpart[(b * 4 + 1) * DD + t] +
               g_qpart[(b * 4 + 2) * DD + t] + g_qpart[(b * 4 + 3) * DD + t]) * (1.f / 128.f);
    qs[t] = s;
    g_q[b * DD + t] = s;
    __syncthreads();
    int w = t >> 5, lane = t & 31;                // 16 warps == RR
    float acc = 0.f;
    for (int i = lane; i < DD; i += 32) acc += qs[i] * loraB[w * DD + i];
#pragma unroll
    for (int o = 16; o; o >>= 1) acc += __shfl_xor_sync(0xffffffffu, acc, o);
    if (lane == 0) g_qB[b * RR + w] = acc;
}

// ---------------- kernel 2: fused scores GEMM + new_mem copy ------------------
// scores[b][n] = dot(q[b], base[n]) + dot(qB[b], A[n])  (lora folded as chunk 8)
// newmem[n]    = base[n]   (copied out of smem during compute)
__device__ __forceinline__ void stage_chunk(int c, float* bsb, float* qcb,
                                            const float* __restrict__ base,
                                            const float* __restrict__ loraA,
                                            int n0, int tid) {
    if (c < 8) {
#pragma unroll
        for (int j = 0; j < 8; j++) {
            int i = tid + j * 256, row = i >> 4, c4 = i & 15;
            cp16(bsb + row * BST + c4 * 4, base + (size_t)(n0 + row) * DD + c * KC + c4 * 4);
        }
#pragma unroll
        for (int j = 0; j < 2; j++) {
            int i = tid + j * 256, b = i >> 4, c4 = i & 15;
            cp16(qcb + b * KC + c4 * 4, g_q + b * DD + c * KC + c4 * 4);
        }
    } else {
#pragma unroll
        for (int j = 0; j < 2; j++) {
            int i = tid + j * 256, row = i >> 2, r4 = i & 3;
            cp16(bsb + row * BST + r4 * 4, loraA + (size_t)(n0 + row) * RR + r4 * 4);
        }
        if (tid < 128) {
            int b = tid >> 2, r4 = tid & 3;
            cp16(qcb + b * KC + r4 * 4, g_qB + b * RR + r4 * 4);
        }
    }
    asm volatile("cp.async.commit_group;" ::: "memory");
}

__global__ void __launch_bounds__(256, 2) k_main(const float* __restrict__ base,
                                                 const float* __restrict__ loraA,
                                                 float* __restrict__ newmem) {
    extern __shared__ float sm[];
    float* bsA = sm;
    float* bsB = sm + NBLK * BST;
    float* qcA = sm + 2 * NBLK * BST;
    float* qcB = qcA + BB * KC;

    int tid = threadIdx.x, n0 = blockIdx.x * NBLK;
    int rg = tid & 31, bg = tid >> 5;

    ull acc[4][4];
#pragma unroll
    for (int bt = 0; bt < 4; bt++)
#pragma unroll
        for (int rt = 0; rt < 4; rt++) acc[bt][rt] = 0ull;

    stage_chunk(0, bsA, qcA, base, loraA, n0, tid);

#pragma unroll 1
    for (int c = 0; c <= 8; c++) {
        float* bsb = (c & 1) ? bsB : bsA;
        float* qcb = (c & 1) ? qcB : qcA;
        if (c < 8) {
            stage_chunk(c + 1, (c & 1) ? bsA : bsB, (c & 1) ? qcA : qcB, base, loraA, n0, tid);
            asm volatile("cp.async.wait_group 1;" ::: "memory");
        } else {
            asm volatile("cp.async.wait_group 0;" ::: "memory");
        }
        __syncthreads();

        if (c < 8) {
            // copy tile out of smem -> newmem (streaming write)
#pragma unroll
            for (int j = 0; j < 8; j++) {
                int i = tid + j * 256, row = i >> 4, c4 = i & 15;
                float4 v = *(const float4*)(bsb + row * BST + c4 * 4);
                *(float4*)(newmem + (size_t)(n0 + row) * DD + c * KC + c4 * 4) = v;
            }
#pragma unroll
            for (int kp4 = 0; kp4 < 16; kp4++) {
                float4 qv[4], bv[4];
#pragma unroll
                for (int bt = 0; bt < 4; bt++)
                    qv[bt] = *(const float4*)(qcb + (bg * 4 + bt) * KC + kp4 * 4);
#pragma unroll
                for (int rt = 0; rt < 4; rt++)
                    bv[rt] = *(const float4*)(bsb + (rg + 32 * rt) * BST + kp4 * 4);
#pragma unroll
                for (int bt = 0; bt < 4; bt++)
#pragma unroll
                    for (int rt = 0; rt < 4; rt++) {
                        const ull* qp = (const ull*)&qv[bt];
                        const ull* bp = (const ull*)&bv[rt];
                        acc[bt][rt] = fma2(qp[0], bp[0], acc[bt][rt]);
                        acc[bt][rt] = fma2(qp[1], bp[1], acc[bt][rt]);
                    }
            }
        } else {
            // lora mini-chunk: k-width 16 (A rows / qB)
#pragma unroll
            for (int kp4 = 0; kp4 < 4; kp4++) {
                float4 qv[4], bv[4];
#pragma unroll
                for (int bt = 0; bt < 4; bt++)
                    qv[bt] = *(const float4*)(qcb + (bg * 4 + bt) * KC + kp4 * 4);
#pragma unroll
                for (int rt = 0; rt < 4; rt++)
                    bv[rt] = *(const float4*)(bsb + (rg + 32 * rt) * BST + kp4 * 4);
#pragma unroll
                for (int bt = 0; bt < 4; bt++)
#pragma unroll
                    for (int rt = 0; rt < 4; rt++) {
                        const ull* qp = (const ull*)&qv[bt];
                        const ull* bp = (const ull*)&bv[rt];
                        acc[bt][rt] = fma2(qp[0], bp[0], acc[bt][rt]);
                        acc[bt][rt] = fma2(qp[1], bp[1], acc[bt][rt]);
                    }
            }
        }
        __syncthreads();
    }

#pragma unroll
    for (int bt = 0; bt < 4; bt++) {
        int b = bg * 4 + bt;
#pragma unroll
        for (int rt = 0; rt < 4; rt++) {
            int rl = rg + 32 * rt;
            g_scores[(size_t)b * NN + n0 + rl] = lo32(acc[bt][rt]) + hi32(acc[bt][rt]);
        }
    }
}

// ---------------- kernel 3: top-8 per batch (JAX semantics) -------------------
__device__ __forceinline__ bool better(float v1, int i1, float v2, int i2) {
    return (v1 > v2) || (v1 == v2 && i1 < i2);
}
__global__ void k_topk() {
    int b = blockIdx.x, tid = threadIdx.x;   // 1024 threads
    extern __shared__ float sm[];
    float* sval = sm;                         // 8192
    int*   sidx = (int*)(sm + 8192);          // 8192
    float* rv   = sm + 16384;                 // 1024
    int*   ri   = (int*)(sm + 17408);         // 1024
    int*   rs   = (int*)(sm + 18432);         // 1024

    const float* sc = g_scores + (size_t)b * NN;
    const float NEG = -__int_as_float(0x7f800000);
    float v[8]; int ix[8];
#pragma unroll
    for (int i = 0; i < 8; i++) { v[i] = NEG; ix[i] = 0x7fffffff; }

    for (int i = 0; i < NN / 1024; i++) {
        int n = tid + (i << 10);
        float x = sc[n];
        if (x > v[7]) {
            v[7] = x; ix[7] = n;
#pragma unroll
            for (int j = 7; j >= 1; j--) {
                if (v[j] > v[j - 1]) {
                    float tv = v[j - 1]; int ti = ix[j - 1];
                    v[j - 1] = v[j]; ix[j - 1] = ix[j];
                    v[j] = tv; ix[j] = ti;
                }
            }
        }
    }
#pragma unroll
    for (int i = 0; i < 8; i++) { sval[tid * 8 + i] = v[i]; sidx[tid * 8 + i] = ix[i]; }
    __syncthreads();

    for (int r = 0; r < KK; r++) {
        float bv = NEG; int bi = 0x7fffffff; int bslot = tid * 8;
#pragma unroll
        for (int i = 0; i < 8; i++) {
            int s = tid * 8 + i;
            if (better(sval[s], sidx[s], bv, bi)) { bv = sval[s]; bi = sidx[s]; bslot = s; }
        }
        rv[tid] = bv; ri[tid] = bi; rs[tid] = bslot;
        __syncthreads();
        for (int s = 512; s > 0; s >>= 1) {
            if (tid < s) {
                if (better(rv[tid + s], ri[tid + s], rv[tid], ri[tid])) {
                    rv[tid] = rv[tid + s]; ri[tid] = ri[tid + s]; rs[tid] = rs[tid + s];
                }
            }
            __syncthreads();
        }
        if (tid == 0) {
            g_topidx[b * KK + r] = ri[0];
            sval[rs[0]] = NEG;   // remove winner
        }
        __syncthreads();
    }
}

// ---------------- kernel 4: retrieved rows (mem = base + A@B) -----------------
__global__ void k_retr(const float* __restrict__ base, const float* __restrict__ loraA,
                       const float* __restrict__ loraB, float* __restrict__ out_retr) {
    int bk = blockIdx.x;                      // 256 blocks: (b, k)
    int d = threadIdx.x;                      // 512 threads
    int idx = g_topidx[bk];
    float vv = base[(size_t)idx * DD + d];
    const float* Arow = loraA + (size_t)idx * RR;
#pragma unroll
    for (int r = 0; r < RR; r++) vv += __ldg(&Arow[r]) * loraB[r * DD + d];
    out_retr[(size_t)bk * DD + d] = vv;
}

// ---------------- kernel 5: xsum (from out_retr) + gx[j][b] -------------------
__global__ void k_gx(const float* __restrict__ w_ih, const float* __restrict__ retr) {
    extern __shared__ float xs[];            // 32*512 floats
    int tid = threadIdx.x;                   // 1024 threads
    for (int i = tid; i < BB * DD; i += 1024) {
        int b = i >> 9, d = i & 511;
        float s = 0.f;
#pragma unroll
        for (int k = 0; k < KK; k++) s += retr[(size_t)(b * KK + k) * DD + d];
        xs[i] = s;
    }
    __syncthreads();
    int w = tid >> 5, lane = tid & 31;
    int j = blockIdx.x * 32 + w;             // 48 blocks * 32 warps = 1536 rows
    const float* wr = w_ih + (size_t)j * DD;
    float acc[BB];
#pragma unroll
    for (int b = 0; b < BB; b++) acc[b] = 0.f;
    for (int kk = 0; kk < DD / 32; kk++) {
        float wv = wr[kk * 32 + lane];
#pragma unroll
        for (int b = 0; b < BB; b++) acc[b] += wv * xs[b * DD + kk * 32 + lane];
    }
#pragma unroll
    for (int b = 0; b < BB; b++) {
        float a = acc[b];
#pragma unroll
        for (int o = 16; o; o >>= 1) a += __shfl_xor_sync(0xffffffffu, a, o);
        if (lane == b) g_gx[j * 32 + b] = a;
    }
}

// ---------------- kernel 6: GRU hidden (h0=0) + write_prob --------------------
__global__ void k_hid_wp(const float* __restrict__ b_ih, const float* __restrict__ b_hh,
                         const float* __restrict__ wg_w, const float* __restrict__ wg_b,
                         float* __restrict__ out_hidden) {
    int b = blockIdx.x, d = threadIdx.x;     // 32 blocks x 512 threads
    __shared__ float red[16];
    float gr = g_gx[(0 * DD + d) * 32 + b] + b_ih[d]          + b_hh[d];
    float gz = g_gx[(1 * DD + d) * 32 + b] + b_ih[DD + d]     + b_hh[DD + d];
    float gn = g_gx[(2 * DD + d) * 32 + b] + b_ih[2 * DD + d];
    float r = sigmoidf_(gr);
    float z = sigmoidf_(gz);
    float n = tanhf(gn + r * b_hh[2 * DD + d]);
    float h = (1.f - z) * n;
    out_hidden[b * DD + d] = h;
    float a = h * wg_w[d];
    int w = d >> 5, lane = d & 31;
#pragma unroll
    for (int o = 16; o; o >>= 1) a += __shfl_xor_sync(0xffffffffu, a, o);
    if (lane == 0) red[w] = a;
    __syncthreads();
    if (w == 0) {
        float v = (lane < 16) ? red[lane] : 0.f;
#pragma unroll
        for (int o = 8; o; o >>= 1) v += __shfl_xor_sync(0xffffffffu, v, o);
        if (lane == 0) g_wp[b] = sigmoidf_(v + wg_b[0]);
    }
}

// ---------------- kernel 7: sequential-over-batch scatter ---------------------
__global__ void k_scatter(float* __restrict__ newmem) {
    int tid = threadIdx.x;                    // 512 threads, single block
    for (int b = 0; b < BB; b++) {
        float p  = g_wp[b];
        float vq = g_q[b * DD + tid];
#pragma unroll
        for (int k = 0; k < KK; k++) {
            size_t row = (size_t)g_topidx[b * KK + k] * DD;
            newmem[row + tid] = (1.f - p) * newmem[row + tid] + p * vq;
        }
        __syncthreads();   // batch b+1 must see batch b's writes (cross-batch collisions)
    }
}

// ---------------- launch ------------------------------------------------------
extern "C" void kernel_launch(void* const* d_in, const int* in_sizes, int n_in,
                              void* d_out, int out_size) {
    const float* query = (const float*)d_in[0];
    const float* base  = (const float*)d_in[1];
    const float* loraA = (const float*)d_in[2];
    const float* loraB = (const float*)d_in[3];
    const float* w_ih  = (const float*)d_in[4];
    // d_in[5] = gru_w_hh : unused (h0 == 0)
    const float* b_ih  = (const float*)d_in[6];
    const float* b_hh  = (const float*)d_in[7];
    const float* wg_w  = (const float*)d_in[8];
    const float* wg_b  = (const float*)d_in[9];

    float* out        = (float*)d_out;
    float* out_retr   = out;                          // [32, 8, 512]
    float* out_hidden = out + BB * KK * DD;           // [32, 512]
    float* out_newmem = out + BB * KK * DD + BB * DD; // [131072, 512]

    const int MAIN_SMEM = (2 * NBLK * BST + 2 * BB * KC) * 4;   // 86,016 B
    const int TOPK_SMEM = (8192 * 2 + 1024 * 3) * 4;            // 77,824 B
    const int GX_SMEM   = BB * DD * 4;                          // 65,536 B
    cudaFuncSetAttribute(k_main, cudaFuncAttributeMaxDynamicSharedMemorySize, MAIN_SMEM);
    cudaFuncSetAttribute(k_topk, cudaFuncAttributeMaxDynamicSharedMemorySize, TOPK_SMEM);
    cudaFuncSetAttribute(k_gx,   cudaFuncAttributeMaxDynamicSharedMemorySize, GX_SMEM);

    k_qsum   <<<dim3(BB, 4), DD>>>(query);
    k_qfin   <<<BB, DD>>>(loraB);
    k_main   <<<NN / NBLK, 256, MAIN_SMEM>>>(base, loraA, out_newmem);
    k_topk   <<<BB, 1024, TOPK_SMEM>>>();
    k_retr   <<<BB * KK, DD>>>(base, loraA, loraB, out_retr);
    k_gx     <<<48, 1024, GX_SMEM>>>(w_ih, out_retr);
    k_hid_wp <<<BB, DD>>>(b_ih, b_hh, wg_w, wg_b, out_hidden);
    k_scatter<<<1, DD>>>(out_newmem);
}